// round 3
// baseline (speedup 1.0000x reference)
#include <cuda_runtime.h>

#define TPTS 32          // points per tile
#define H    256
#define EDIM 63
#define PSTR 36          // padded point-stride in shared (floats); 144B = 16B-aligned

typedef unsigned long long u64;

// ---- packed f32x2 helpers (FFMA2: PTX-only on sm_103a) ----
__device__ __forceinline__ u64 pk2(float w) {
    u64 r; asm("mov.b64 %0, {%1, %1};" : "=l"(r) : "f"(w)); return r;
}
__device__ __forceinline__ void fma2(u64 &a, u64 x, u64 w) {
    asm("fma.rn.f32x2 %0, %1, %2, %0;" : "+l"(a) : "l"(x), "l"(w));
}
__device__ __forceinline__ u64 add2(u64 a, u64 b) {
    u64 r; asm("add.rn.f32x2 %0, %1, %2;" : "=l"(r) : "l"(a), "l"(b)); return r;
}
__device__ __forceinline__ u64 mul2(u64 a, u64 b) {
    u64 r; asm("mul.rn.f32x2 %0, %1, %2;" : "=l"(r) : "l"(a), "l"(b)); return r;
}
__device__ __forceinline__ u64 relu2(u64 a) {
    float lo, hi;
    asm("mov.b64 {%0, %1}, %2;" : "=f"(lo), "=f"(hi) : "l"(a));
    lo = fmaxf(lo, 0.0f); hi = fmaxf(hi, 0.0f);
    u64 r; asm("mov.b64 %0, {%1, %2};" : "=l"(r) : "f"(lo), "f"(hi)); return r;
}
struct __align__(16) u64x2 { u64 x, y; };

// shared layout (floats): c_s[96] | e_s[63*36] | x_s[256*36] | y_s[256*36] | occ_s[256] | prt_s[256]
#define OFF_C   0
#define OFF_E   96
#define OFF_X   (96 + EDIM*PSTR)            // 2364
#define OFF_Y   (OFF_X + H*PSTR)            // 11580
#define OFF_OCC (OFF_Y + H*PSTR)            // 20796
#define OFF_PRT (OFF_OCC + 256)             // 21052
#define SMEM_FLOATS (OFF_PRT + 256)         // 21308
#define SMEM_BYTES  (SMEM_FLOATS * 4)       // 85232

__global__ void __launch_bounds__(256, 2) mlp3d_kernel(
    const float* __restrict__ coords,
    const float* __restrict__ W0, const float* __restrict__ b0,
    const float* __restrict__ W1, const float* __restrict__ b1,
    const float* __restrict__ W2, const float* __restrict__ b2,
    const float* __restrict__ Wocc, const float* __restrict__ bocc,
    const float* __restrict__ Wc, const float* __restrict__ bc,
    float* __restrict__ out, int N)
{
    extern __shared__ float sm[];
    float* c_s   = sm + OFF_C;
    float* e_s   = sm + OFF_E;
    float* x_s   = sm + OFF_X;
    float* y_s   = sm + OFF_Y;
    float* occ_s = sm + OFF_OCC;
    float* prt_s = sm + OFF_PRT;

    const int t    = threadIdx.x;
    const int lane = t & 31;
    const int warp = t >> 5;
    const int n0   = blockIdx.x * TPTS;

    // --- load coords for this tile ---
    if (t < 3 * TPTS) c_s[t] = coords[n0 * 3 + t];
    __syncthreads();

    // --- NeRF positional embedding into e_s[i][m] ---
    // e order: [x0,x1,x2] then, for f=0..9: sin(2^f * x0..x2), cos(2^f * x0..x2)
    for (int idx = t; idx < EDIM * TPTS; idx += 256) {
        int i = idx >> 5, m = idx & 31;
        float v;
        if (i < 3) {
            v = c_s[m * 3 + i];
        } else {
            int k = i - 3;
            int f = k / 6;
            int r = k - 6 * f;          // 0..5 : [sin x3, cos x3]
            int c = (r >= 3) ? (r - 3) : r;
            float arg = c_s[m * 3 + c] * (float)(1 << f);
            float sv, cv;
            sincosf(arg, &sv, &cv);
            v = (r < 3) ? sv : cv;
        }
        e_s[i * PSTR + m] = v;
    }
    __syncthreads();

    const int j = t;                 // this thread's output neuron
    u64 acc[16];

    // =================== layer 0: x = e @ W0 + b0 (no relu) ===================
    {
        u64 b = pk2(b0[j]);
        #pragma unroll
        for (int k = 0; k < 16; k++) acc[k] = b;
        #pragma unroll 3
        for (int i = 0; i < EDIM; i++) {
            u64 w = pk2(W0[i * H + j]);
            const u64x2* row = (const u64x2*)(e_s + i * PSTR);
            #pragma unroll
            for (int k = 0; k < 8; k++) {
                u64x2 v = row[k];
                fma2(acc[2 * k],     v.x, w);
                fma2(acc[2 * k + 1], v.y, w);
            }
        }
        u64* xr = (u64*)(x_s + j * PSTR);
        #pragma unroll
        for (int k = 0; k < 16; k++) xr[k] = acc[k];
    }
    __syncthreads();

    // =================== layer 1 (occ trunk): y = relu(x @ W1 + b1) ===================
    {
        u64 b = pk2(b1[j]);
        #pragma unroll
        for (int k = 0; k < 16; k++) acc[k] = b;
        #pragma unroll 4
        for (int i = 0; i < H; i++) {
            u64 w = pk2(W1[i * H + j]);
            const u64x2* row = (const u64x2*)(x_s + i * PSTR);
            #pragma unroll
            for (int k = 0; k < 8; k++) {
                u64x2 v = row[k];
                fma2(acc[2 * k],     v.x, w);
                fma2(acc[2 * k + 1], v.y, w);
            }
        }
        u64* yr = (u64*)(y_s + j * PSTR);
        #pragma unroll
        for (int k = 0; k < 16; k++) yr[k] = relu2(acc[k]);
    }
    __syncthreads();

    // =================== layer 2 + occ head: z = relu(y @ W2 + b2); occ = z @ Wocc + bocc ===================
    {
        u64 b = pk2(b2[j]);
        #pragma unroll
        for (int k = 0; k < 16; k++) acc[k] = b;
        #pragma unroll 4
        for (int i = 0; i < H; i++) {
            u64 w = pk2(W2[i * H + j]);
            const u64x2* row = (const u64x2*)(y_s + i * PSTR);
            #pragma unroll
            for (int k = 0; k < 8; k++) {
                u64x2 v = row[k];
                fma2(acc[2 * k],     v.x, w);
                fma2(acc[2 * k + 1], v.y, w);
            }
        }
        u64 wo = pk2(Wocc[j]);
        #pragma unroll
        for (int k = 0; k < 16; k++) acc[k] = mul2(relu2(acc[k]), wo);
        // butterfly reduce over the 32 lanes (32 neurons) of this warp
        #pragma unroll
        for (int off = 16; off; off >>= 1) {
            #pragma unroll
            for (int k = 0; k < 16; k++)
                acc[k] = add2(acc[k], __shfl_xor_sync(0xffffffffu, acc[k], off));
        }
        if (lane < 16) ((u64*)occ_s)[warp * 16 + lane] = acc[lane];
    }
    __syncthreads();
    if (t < TPTS) {
        float o = bocc[0];
        #pragma unroll
        for (int w = 0; w < 8; w++) o += occ_s[w * 32 + t];
        out[n0 + t] = o;                       // occ output: first N floats
    }

    // =================== part branches (block-diagonal): h = relu(x[s0:s0+64] @ W1[s0:s0+64, j] + b1) ===================
    {
        const int p  = j >> 6;
        const int s0 = p << 6;
        u64 b = pk2(b1[j]);
        #pragma unroll
        for (int k = 0; k < 16; k++) acc[k] = b;
        #pragma unroll 4
        for (int i = s0; i < s0 + 64; i++) {
            u64 w = pk2(W1[i * H + j]);
            const u64x2* row = (const u64x2*)(x_s + i * PSTR);
            #pragma unroll
            for (int k = 0; k < 8; k++) {
                u64x2 v = row[k];
                fma2(acc[2 * k],     v.x, w);
                fma2(acc[2 * k + 1], v.y, w);
            }
        }
        u64 wc = pk2(Wc[p * H + j]);
        #pragma unroll
        for (int k = 0; k < 16; k++) acc[k] = mul2(relu2(acc[k]), wc);
        #pragma unroll
        for (int off = 16; off; off >>= 1) {
            #pragma unroll
            for (int k = 0; k < 16; k++)
                acc[k] = add2(acc[k], __shfl_xor_sync(0xffffffffu, acc[k], off));
        }
        if (lane < 16) ((u64*)prt_s)[warp * 16 + lane] = acc[lane];
    }
    __syncthreads();
    if (t < 4 * TPTS) {
        int m = t & 31, p = t >> 5;            // part = 2 warps -> sum both halves
        float v = prt_s[(2 * p) * 32 + m] + prt_s[(2 * p + 1) * 32 + m] + bc[p];
        out[N + (n0 + m) * 4 + p] = v;         // part_class: [N,4] row-major after occ
    }
}

extern "C" void kernel_launch(void* const* d_in, const int* in_sizes, int n_in,
                              void* d_out, int out_size) {
    const float* coords = (const float*)d_in[0];
    const float* W0   = (const float*)d_in[1];
    const float* b0   = (const float*)d_in[2];
    const float* W1   = (const float*)d_in[3];
    const float* b1   = (const float*)d_in[4];
    const float* W2   = (const float*)d_in[5];
    const float* b2   = (const float*)d_in[6];
    const float* Wocc = (const float*)d_in[7];
    const float* bocc = (const float*)d_in[8];
    const float* Wc   = (const float*)d_in[9];
    const float* bc   = (const float*)d_in[10];
    float* out = (float*)d_out;

    int N = in_sizes[0] / 3;        // 131072
    int tiles = N / TPTS;           // 4096

    cudaFuncSetAttribute(mlp3d_kernel,
                         cudaFuncAttributeMaxDynamicSharedMemorySize, SMEM_BYTES);
    mlp3d_kernel<<<tiles, 256, SMEM_BYTES>>>(
        coords, W0, b0, W1, b1, W2, b2, Wocc, bocc, Wc, bc, out, N);
}

// round 4
// speedup vs baseline: 2.6762x; 2.6762x over previous
#include <cuda_runtime.h>

#define TPTS 32          // points per tile
#define H    256
#define EDIM 63
#define PSTR 36          // padded point-stride in shared (floats); 144B (16B-aligned rows)

typedef unsigned long long u64;
struct __align__(16) u64x2 { u64 x, y; };

// ---- packed f32x2 helpers (FFMA2 is PTX-only on sm_103a) ----
__device__ __forceinline__ u64 pk2(float w) {
    u64 r; asm("mov.b64 %0, {%1, %1};" : "=l"(r) : "f"(w)); return r;
}
__device__ __forceinline__ void fma2(u64 &a, u64 x, u64 w) {
    asm("fma.rn.f32x2 %0, %1, %2, %0;" : "+l"(a) : "l"(x), "l"(w));
}
__device__ __forceinline__ u64 add2(u64 a, u64 b) {
    u64 r; asm("add.rn.f32x2 %0, %1, %2;" : "=l"(r) : "l"(a), "l"(b)); return r;
}
__device__ __forceinline__ u64 mul2(u64 a, u64 b) {
    u64 r; asm("mul.rn.f32x2 %0, %1, %2;" : "=l"(r) : "l"(a), "l"(b)); return r;
}
__device__ __forceinline__ u64 relu2(u64 a) {
    float lo, hi;
    asm("mov.b64 {%0, %1}, %2;" : "=f"(lo), "=f"(hi) : "l"(a));
    lo = fmaxf(lo, 0.0f); hi = fmaxf(hi, 0.0f);
    u64 r; asm("mov.b64 %0, {%1, %2};" : "=l"(r) : "f"(lo), "f"(hi)); return r;
}
__device__ __forceinline__ u64 shfl_xor_u64(u64 v, int off) {
    unsigned lo = (unsigned)v, hi = (unsigned)(v >> 32);
    lo = __shfl_xor_sync(0xffffffffu, lo, off);
    hi = __shfl_xor_sync(0xffffffffu, hi, off);
    return ((u64)hi << 32) | lo;
}

// Accumulate acc[jj*4+kk] += in[i][m0+2kk..] * W[i][j0+jj] over i in [i0, i0+ni)
// acc layout: neuron jj (0..3) x point-pair kk (0..3, points m0+2kk, m0+2kk+1)
__device__ __forceinline__ void accum(u64 acc[16], const float* __restrict__ W,
                                      const float* in_s, int i0, int ni,
                                      int j0, int m0)
{
    #pragma unroll 4
    for (int i = i0; i < i0 + ni; i++) {
        float4 wv = *(const float4*)(W + i * H + j0);       // LDG.128: 4 neuron weights
        u64 w0 = pk2(wv.x), w1 = pk2(wv.y), w2 = pk2(wv.z), w3 = pk2(wv.w);
        const u64x2* row = (const u64x2*)(in_s + i * PSTR + m0);
        u64x2 a = row[0], b = row[1];                        // 2x LDS.128: 8 points
        fma2(acc[0],  a.x, w0); fma2(acc[1],  a.y, w0); fma2(acc[2],  b.x, w0); fma2(acc[3],  b.y, w0);
        fma2(acc[4],  a.x, w1); fma2(acc[5],  a.y, w1); fma2(acc[6],  b.x, w1); fma2(acc[7],  b.y, w1);
        fma2(acc[8],  a.x, w2); fma2(acc[9],  a.y, w2); fma2(acc[10], b.x, w2); fma2(acc[11], b.y, w2);
        fma2(acc[12], a.x, w3); fma2(acc[13], a.y, w3); fma2(acc[14], b.x, w3); fma2(acc[15], b.y, w3);
    }
}

// shared layout (floats)
#define OFF_C   0
#define OFF_E   96
#define OFF_X   (OFF_E + EDIM * PSTR)       // 2364
#define OFF_Y   (OFF_X + H * PSTR)          // 11580
#define OFF_OCC (OFF_Y + H * PSTR)          // 20796  (64 floats: 8 warps x 8 pts)
#define OFF_CLS (OFF_OCC + 64)              // 20860  (128 floats: 4 parts x 32 pts)
#define SMEM_FLOATS (OFF_CLS + 128)         // 20988
#define SMEM_BYTES  (SMEM_FLOATS * 4)       // 83952

__global__ void __launch_bounds__(256, 2) mlp3d_kernel(
    const float* __restrict__ coords,
    const float* __restrict__ W0, const float* __restrict__ b0,
    const float* __restrict__ W1, const float* __restrict__ b1,
    const float* __restrict__ W2, const float* __restrict__ b2,
    const float* __restrict__ Wocc, const float* __restrict__ bocc,
    const float* __restrict__ Wc, const float* __restrict__ bc,
    float* __restrict__ out, int N)
{
    extern __shared__ float sm[];
    float* c_s   = sm + OFF_C;
    float* e_s   = sm + OFF_E;
    float* x_s   = sm + OFF_X;
    float* y_s   = sm + OFF_Y;
    float* occ_s = sm + OFF_OCC;
    float* cls_s = sm + OFF_CLS;

    const int t    = threadIdx.x;
    const int lane = t & 31;
    const int warp = t >> 5;
    const int nq   = t & 63;     // neuron quad: neurons j0..j0+3
    const int pg   = t >> 6;     // point group: points m0..m0+7
    const int j0   = nq << 2;
    const int m0   = pg << 3;
    const int n0   = blockIdx.x * TPTS;

    // --- load coords for this tile ---
    if (t < 3 * TPTS) c_s[t] = coords[n0 * 3 + t];
    __syncthreads();

    // --- NeRF positional embedding into e_s[i][m] ---
    for (int idx = t; idx < EDIM * TPTS; idx += 256) {
        int i = idx >> 5, m = idx & 31;
        float v;
        if (i < 3) {
            v = c_s[m * 3 + i];
        } else {
            int k = i - 3;
            int f = k / 6;
            int r = k - 6 * f;                  // 0..5 : [sin x3, cos x3]
            int c = (r >= 3) ? (r - 3) : r;
            float arg = c_s[m * 3 + c] * (float)(1 << f);
            float sv, cv;
            sincosf(arg, &sv, &cv);
            v = (r < 3) ? sv : cv;
        }
        e_s[i * PSTR + m] = v;
    }
    __syncthreads();

    u64 acc[16];

    // =================== layer 0: x = e @ W0 + b0 (no relu) ===================
    {
        float4 bv = *(const float4*)(b0 + j0);
        u64 bb[4] = {pk2(bv.x), pk2(bv.y), pk2(bv.z), pk2(bv.w)};
        #pragma unroll
        for (int jj = 0; jj < 4; jj++)
            #pragma unroll
            for (int kk = 0; kk < 4; kk++) acc[jj * 4 + kk] = bb[jj];
        accum(acc, W0, e_s, 0, EDIM, j0, m0);
        #pragma unroll
        for (int jj = 0; jj < 4; jj++) {
            u64x2* xr = (u64x2*)(x_s + (j0 + jj) * PSTR + m0);
            u64x2 v0; v0.x = acc[jj * 4 + 0]; v0.y = acc[jj * 4 + 1];
            u64x2 v1; v1.x = acc[jj * 4 + 2]; v1.y = acc[jj * 4 + 3];
            xr[0] = v0; xr[1] = v1;
        }
    }
    __syncthreads();

    // =================== layer 1 (occ trunk): y = relu(x @ W1 + b1) ===================
    {
        float4 bv = *(const float4*)(b1 + j0);
        u64 bb[4] = {pk2(bv.x), pk2(bv.y), pk2(bv.z), pk2(bv.w)};
        #pragma unroll
        for (int jj = 0; jj < 4; jj++)
            #pragma unroll
            for (int kk = 0; kk < 4; kk++) acc[jj * 4 + kk] = bb[jj];
        accum(acc, W1, x_s, 0, H, j0, m0);
        #pragma unroll
        for (int jj = 0; jj < 4; jj++) {
            u64x2* yr = (u64x2*)(y_s + (j0 + jj) * PSTR + m0);
            u64x2 v0; v0.x = relu2(acc[jj * 4 + 0]); v0.y = relu2(acc[jj * 4 + 1]);
            u64x2 v1; v1.x = relu2(acc[jj * 4 + 2]); v1.y = relu2(acc[jj * 4 + 3]);
            yr[0] = v0; yr[1] = v1;
        }
    }
    __syncthreads();

    // ========== layer 2 + occ head: z = relu(y @ W2 + b2); occ += z . Wocc ==========
    {
        float4 bv = *(const float4*)(b2 + j0);
        u64 bb[4] = {pk2(bv.x), pk2(bv.y), pk2(bv.z), pk2(bv.w)};
        #pragma unroll
        for (int jj = 0; jj < 4; jj++)
            #pragma unroll
            for (int kk = 0; kk < 4; kk++) acc[jj * 4 + kk] = bb[jj];
        accum(acc, W2, y_s, 0, H, j0, m0);

        float4 wv = *(const float4*)(Wocc + j0);
        u64 w0 = pk2(wv.x), w1 = pk2(wv.y), w2 = pk2(wv.z), w3 = pk2(wv.w);
        u64 s[4];
        #pragma unroll
        for (int kk = 0; kk < 4; kk++) {
            s[kk] = mul2(relu2(acc[kk]), w0);
            fma2(s[kk], relu2(acc[4 + kk]),  w1);
            fma2(s[kk], relu2(acc[8 + kk]),  w2);
            fma2(s[kk], relu2(acc[12 + kk]), w3);
        }
        // reduce 32 quads of this warp (full butterfly)
        #pragma unroll
        for (int off = 16; off; off >>= 1)
            #pragma unroll
            for (int kk = 0; kk < 4; kk++)
                s[kk] = add2(s[kk], shfl_xor_u64(s[kk], off));
        if (lane == 0) {
            u64* o = (u64*)occ_s;            // occ_s[warp][8 pts]
            #pragma unroll
            for (int kk = 0; kk < 4; kk++) o[warp * 4 + kk] = s[kk];
        }
    }

    // ========== part branch (block-diagonal): cls[p] = (relu(x[p-blk] @ W1[p-blk] + b1) . Wc[p]) ==========
    {
        const int p  = nq >> 4;              // part of this quad
        const int i0 = p << 6;
        float4 bv = *(const float4*)(b1 + j0);
        u64 bb[4] = {pk2(bv.x), pk2(bv.y), pk2(bv.z), pk2(bv.w)};
        #pragma unroll
        for (int jj = 0; jj < 4; jj++)
            #pragma unroll
            for (int kk = 0; kk < 4; kk++) acc[jj * 4 + kk] = bb[jj];
        accum(acc, W1, x_s, i0, 64, j0, m0);

        float4 wv = *(const float4*)(Wc + p * H + j0);
        u64 w0 = pk2(wv.x), w1 = pk2(wv.y), w2 = pk2(wv.z), w3 = pk2(wv.w);
        u64 s[4];
        #pragma unroll
        for (int kk = 0; kk < 4; kk++) {
            s[kk] = mul2(relu2(acc[kk]), w0);
            fma2(s[kk], relu2(acc[4 + kk]),  w1);
            fma2(s[kk], relu2(acc[8 + kk]),  w2);
            fma2(s[kk], relu2(acc[12 + kk]), w3);
        }
        // each part's 16 quads sit in one half-warp -> 4-round butterfly
        #pragma unroll
        for (int off = 8; off; off >>= 1)
            #pragma unroll
            for (int kk = 0; kk < 4; kk++)
                s[kk] = add2(s[kk], shfl_xor_u64(s[kk], off));
        if ((lane & 15) == 0) {
            u64* c = (u64*)cls_s;            // cls_s[p][32 pts]
            #pragma unroll
            for (int kk = 0; kk < 4; kk++) c[p * 16 + (m0 >> 1) + kk] = s[kk];
        }
    }
    __syncthreads();

    // --- final writes ---
    if (t < TPTS) {
        int g = t >> 3, r = t & 7;
        float o = bocc[0] + occ_s[(2 * g) * 8 + r] + occ_s[(2 * g + 1) * 8 + r];
        out[n0 + t] = o;                                   // occ: first N floats
    }
    if (t < 4 * TPTS) {
        int p = t >> 5, m = t & 31;
        out[N + (n0 + m) * 4 + p] = cls_s[p * 32 + m] + bc[p];   // part_class [N,4]
    }
}

extern "C" void kernel_launch(void* const* d_in, const int* in_sizes, int n_in,
                              void* d_out, int out_size) {
    const float* coords = (const float*)d_in[0];
    const float* W0   = (const float*)d_in[1];
    const float* b0   = (const float*)d_in[2];
    const float* W1   = (const float*)d_in[3];
    const float* b1   = (const float*)d_in[4];
    const float* W2   = (const float*)d_in[5];
    const float* b2   = (const float*)d_in[6];
    const float* Wocc = (const float*)d_in[7];
    const float* bocc = (const float*)d_in[8];
    const float* Wc   = (const float*)d_in[9];
    const float* bc   = (const float*)d_in[10];
    float* out = (float*)d_out;

    int N = in_sizes[0] / 3;        // 131072
    int tiles = N / TPTS;           // 4096

    cudaFuncSetAttribute(mlp3d_kernel,
                         cudaFuncAttributeMaxDynamicSharedMemorySize, SMEM_BYTES);
    mlp3d_kernel<<<tiles, 256, SMEM_BYTES>>>(
        coords, W0, b0, W1, b1, W2, b2, Wocc, bocc, Wc, bc, out, N);
}